// round 14
// baseline (speedup 1.0000x reference)
#include <cuda_runtime.h>
#include <cuda_fp16.h>
#include <math.h>

// Problem constants
#define BS_      4096
#define IN_DIM_  2048
#define NN       16384
#define TOTAL_D_ 129      // 1 (dc) + 64 (pairs) + 64 (slack)
#define KPAD     136      // gemm1 accumulator row count
#define KT16     9        // gemm2 k-chunks of 16 (144 padded)

// Scratch (static device globals -- no dynamic allocation allowed)
__device__ float g_hacc[KPAD * BS_];           // [j][b] fp32 gemm1 accumulator
__device__ float g_dc[BS_];                    // exact fp32 h[:,0]
__device__ int   g_cnt[32];                    // per-m-tile split-K counters
// fp16 fragment-shuffled operands for mma.m16n8k16:
//  g_hF[m16][kt][lane] = {a0,a1,a2,a3} packed half2   (A = h[b][j])
//  g_MF[n16][kt][lane] = {b0lo,b1lo,b0hi,b1hi}        (B = M[n][j])
__device__ uint4 g_hF[(BS_ / 16) * KT16 * 32]; // 1.2 MB
__device__ uint4 g_MF[(NN  / 16) * KT16 * 32]; // 4.7 MB

__device__ __forceinline__ void mma_f16(float* c, const unsigned* a, const unsigned* b) {
    asm volatile(
        "mma.sync.aligned.m16n8k16.row.col.f32.f16.f16.f32 "
        "{%0,%1,%2,%3}, {%4,%5,%6,%7}, {%8,%9}, {%0,%1,%2,%3};\n"
        : "+f"(c[0]), "+f"(c[1]), "+f"(c[2]), "+f"(c[3])
        : "r"(a[0]), "r"(a[1]), "r"(a[2]), "r"(a[3]), "r"(b[0]), "r"(b[1]));
}

__device__ __forceinline__ void cp16(void* smem, const void* gptr) {
    unsigned s = (unsigned)__cvta_generic_to_shared(smem);
    asm volatile("cp.async.cg.shared.global [%0], [%1], 16;" :: "r"(s), "l"(gptr));
}
#define CP_COMMIT() asm volatile("cp.async.commit_group;")
#define CP_WAIT(n)  asm volatile("cp.async.wait_group %0;" :: "n"(n))

__device__ __forceinline__ unsigned packh2(float lo, float hi) {
    __half2 p = __floats2half2_rn(lo, hi);
    return *(unsigned*)&p;
}

// ---------------------------------------------------------------------------
// Fused kernel 1: blocks [0, 512)   -> gemm1 (cp.async pipelined, fp16 MMA)
//                                      + last-block-per-m-tile fused finalize
//                 blocks [512, 640) -> basis fragments (rotation recurrence)
// g_hacc and g_cnt are zeroed beforehand by cudaMemsetAsync nodes.
// ---------------------------------------------------------------------------
#define G1_BLOCKS    512                       // 32 m-tiles x 16 k-segs
#define BASIS_BLOCKS (NN / 128)                // 128 (128 n-rows per block)
#define ROWSTRIDE    152                       // basis staging stride (halves)

#define RS       20                            // gemm1 tile row stride (words)
#define A_WORDS  (128 * RS)
#define B_WORDS  (144 * RS)
#define STG_W    (A_WORDS + B_WORDS)
#define G1ST     4
#define PG1_SMEM (G1ST * STG_W * 4)            // 87040 bytes

__global__ __launch_bounds__(256, 2)
void prep_gemm1_kernel(const float* __restrict__ x, const float* __restrict__ W,
                       const float* __restrict__ Ws, const float* __restrict__ bp) {
    extern __shared__ __align__(16) float smf[];
    const int tid = threadIdx.x;

    if (blockIdx.x >= G1_BLOCKS) {
        // ---- basis: M[n][j] rows via rotation recurrence ----
        const int blk = blockIdx.x - G1_BLOCKS;
        __half* Sb = (__half*)smf;
        const int nl = tid >> 1, half = tid & 1;
        const int n  = blk * 128 + nl;
        __half* row = Sb + nl * ROWSTRIDE;

        const float s2i = 1.41421356237309515f * 0.0078125f;  // sqrt2/128
        const float w0  = 6.28318530717958647692f / (float)NN;

        const int k0 = half ? 17 : 1;
        int m0 = (k0 * n) & (NN - 1); if (m0 >= NN / 2) m0 -= NN;
        int m1 = n;                   if (m1 >= NN / 2) m1 -= NN;
        float c, s, c1, s1;
        sincosf((float)m0 * w0, &s,  &c);    // precise seeds: drift < fp16 ulp
        sincosf((float)m1 * w0, &s1, &c1);
#pragma unroll
        for (int i = 0; i < 16; i++) {
            int k = k0 + i;
            row[2 * k - 1] = __float2half_rn(s2i * c);
            row[2 * k]     = __float2half_rn(s2i * s);
            float cn = fmaf(c, c1, -s * s1);
            float sn = fmaf(s, c1,  c * s1);
            c = cn; s = sn;
        }
        const float4* wsrow = (const float4*)(Ws + (size_t)n * 64 + half * 32);
#pragma unroll
        for (int q = 0; q < 8; q++) {
            float4 v = wsrow[q];
            int j = 65 + half * 32 + 4 * q;
            row[j]     = __float2half_rn(v.x);
            row[j + 1] = __float2half_rn(v.y);
            row[j + 2] = __float2half_rn(v.z);
            row[j + 3] = __float2half_rn(v.w);
        }
        if (half == 0) {
            row[0] = __float2half_rn(0.0f);          // DC col (exact in epilogue)
        } else {
#pragma unroll
            for (int j = TOTAL_D_; j < 144; j++)     // pad cols 129..143
                row[j] = __float2half_rn(0.0f);
        }
        __syncthreads();

        // re-emit in mma B-fragment layout
        const int warp = tid >> 5, lane = tid & 31;
        const int g = lane >> 2, t = lane & 3;
        const unsigned* SW = (const unsigned*)Sb;
        const int rlo = (warp * 16 + g) * (ROWSTRIDE / 2);
        const int rhi = rlo + 8 * (ROWSTRIDE / 2);
        const int n16 = blk * 8 + warp;
#pragma unroll
        for (int kt = 0; kt < KT16; kt++) {
            int o = kt * 8 + t;
            g_MF[((size_t)n16 * KT16 + kt) * 32 + lane] =
                make_uint4(SW[rlo + o], SW[rlo + o + 4],
                           SW[rhi + o], SW[rhi + o + 4]);
        }
        return;
    }

    // ---- gemm1: hacc[j][b] += sum_k x[b][k] * W[j][k] (split-K atomics) ----
    const int bid  = blockIdx.x;
    const int mtile   = bid & 31;
    const int rowBase = mtile * 128;
    const int kSeg    = (bid >> 5) * 128;
    const int warp = tid >> 5, lane = tid & 31;
    const int wM = warp & 3, wN = warp >> 2;
    const int m0 = wM * 32, n0 = wN * 72;
    const int g = lane >> 2, t = lane & 3;

#pragma unroll
    for (int st = 0; st < G1ST; st++)
        for (int i = tid; i < 15 * RS; i += 256)
            smf[st * STG_W + A_WORDS + 129 * RS + i] = 0.0f;

    float acc[2][9][4];
#pragma unroll
    for (int mi = 0; mi < 2; mi++)
#pragma unroll
        for (int ni = 0; ni < 9; ni++)
#pragma unroll
            for (int q = 0; q < 4; q++) acc[mi][ni][q] = 0.0f;

    auto load_stage = [&](int st, int chunk) {
        float* Sa = smf + st * STG_W;
        float* Sb = smf + st * STG_W + A_WORDS;
        const int kBase = kSeg + chunk * 16;
#pragma unroll
        for (int i = tid; i < 512; i += 256) {
            int r = i >> 2, q = i & 3;
            cp16(&Sa[r * RS + 4 * q],
                 &x[(size_t)(rowBase + r) * IN_DIM_ + kBase + 4 * q]);
        }
        for (int i = tid; i < 516; i += 256) {
            int j = i >> 2, q = i & 3;
            cp16(&Sb[j * RS + 4 * q],
                 &W[(size_t)j * IN_DIM_ + kBase + 4 * q]);
        }
    };

#pragma unroll
    for (int s = 0; s < 2; s++) { load_stage(s, s); CP_COMMIT(); }

    for (int kc = 0; kc < 8; kc++) {
        if (kc + 2 < 8) load_stage((kc + 2) % G1ST, kc + 2);
        CP_COMMIT();
        CP_WAIT(2);
        __syncthreads();

        const float* Sa = smf + (kc % G1ST) * STG_W;
        const float* Sb = smf + (kc % G1ST) * STG_W + A_WORDS;

        unsigned a[2][4], b[9][2];
#pragma unroll
        for (int mi = 0; mi < 2; mi++) {
            int r = m0 + mi * 16 + g;
            float2 v0 = *(const float2*)&Sa[(r)     * RS + 2 * t];
            float2 v1 = *(const float2*)&Sa[(r + 8) * RS + 2 * t];
            float2 v2 = *(const float2*)&Sa[(r)     * RS + 2 * t + 8];
            float2 v3 = *(const float2*)&Sa[(r + 8) * RS + 2 * t + 8];
            a[mi][0] = packh2(v0.x, v0.y);
            a[mi][1] = packh2(v1.x, v1.y);
            a[mi][2] = packh2(v2.x, v2.y);
            a[mi][3] = packh2(v3.x, v3.y);
        }
#pragma unroll
        for (int ni = 0; ni < 9; ni++) {
            int c = n0 + ni * 8 + g;
            float2 v0 = *(const float2*)&Sb[c * RS + 2 * t];
            float2 v1 = *(const float2*)&Sb[c * RS + 2 * t + 8];
            b[ni][0] = packh2(v0.x, v0.y);
            b[ni][1] = packh2(v1.x, v1.y);
        }
#pragma unroll
        for (int mi = 0; mi < 2; mi++)
#pragma unroll
            for (int ni = 0; ni < 9; ni++)
                mma_f16(acc[mi][ni], a[mi], b[ni]);
    }

#pragma unroll
    for (int mi = 0; mi < 2; mi++) {
        int r = rowBase + m0 + mi * 16 + g;
#pragma unroll
        for (int ni = 0; ni < 9; ni++) {
            int col = n0 + ni * 8 + 2 * t;
            if (col < KPAD) {
                atomicAdd(&g_hacc[(size_t)col * BS_ + r],           acc[mi][ni][0]);
                atomicAdd(&g_hacc[(size_t)(col + 1) * BS_ + r],     acc[mi][ni][1]);
                atomicAdd(&g_hacc[(size_t)col * BS_ + r + 8],       acc[mi][ni][2]);
                atomicAdd(&g_hacc[(size_t)(col + 1) * BS_ + r + 8], acc[mi][ni][3]);
            }
        }
    }

    // ---- fused finalize: last split-K block of this m-tile emits g_hF ----
    __threadfence();
    __shared__ int s_win;
    if (tid == 0) s_win = (atomicAdd(&g_cnt[mtile], 1) == 15);
    __syncthreads();
    if (!s_win) return;
    __threadfence();

    const int m16 = mtile * 8 + warp;    // warp -> m16 within this tile
#pragma unroll
    for (int kt = 0; kt < KT16; kt++) {
        int j0 = 16 * kt + 2 * t;
        unsigned r[4];
#pragma unroll
        for (int ksel = 0; ksel < 2; ksel++) {
            int ja = j0 + ksel * 8, jb = ja + 1;
#pragma unroll
            for (int rsel = 0; rsel < 2; rsel++) {
                int b = m16 * 16 + rsel * 8 + g;
                float va = 0.0f, vb = 0.0f;
                if (ja == 0) {
                    g_dc[b] = g_hacc[b] + __ldg(&bp[0]);      // exact fp32 DC
                } else if (ja < TOTAL_D_) {
                    va = g_hacc[(size_t)ja * BS_ + b] + __ldg(&bp[ja]);
                }
                if (jb < TOTAL_D_)
                    vb = g_hacc[(size_t)jb * BS_ + b] + __ldg(&bp[jb]);
                r[ksel * 2 + rsel] = packh2(va, vb);
            }
        }
        g_hF[((size_t)m16 * KT16 + kt) * 32 + lane] = make_uint4(r[0], r[1], r[2], r[3]);
    }
}

// ---------------------------------------------------------------------------
// GEMM2 (fp16 MMA, persistent): out[b][n] = sum_j h[b][j]*M[n][j] + dc[b]/128
// Grid (9 n-chunks, 32 m-tiles) = 288 CTAs = one resident wave (2/SM).
// Each CTA: A tile loaded ONCE; B streamed as one flattened pipeline over
// 14-15 consecutive n-tiles (4-slot ring, lookahead 2, one barrier/stage).
// Block tile 128(m) x 128(n); 8 warps 2(m) x 4(n); warp 64x32.
// ---------------------------------------------------------------------------
#define ST 4
#define G2_SMEM ((8 * KT16 * 32 + ST * 8 * 32) * 16)   // 53248 bytes
__global__ __launch_bounds__(256, 2)
void gemm2_persist_kernel(float* __restrict__ out) {
    extern __shared__ uint4 smem[];
    uint4* As = smem;                  // [m16rel][kt][lane] = [8][9][32]
    uint4* Bs = smem + 8 * KT16 * 32;  // [slot][n16rel][lane] = [ST][8][32]

    const int chunk = blockIdx.x;      // 0..8
    const int mtile = blockIdx.y;      // 0..31
    const int tid  = threadIdx.x;
    const int warp = tid >> 5, lane = tid & 31;
    const int wM = warp & 1, wN = warp >> 1;     // 2(m) x 4(n)
    const int g = lane >> 2, t = lane & 3;

    // n-tile range for this chunk: chunks 0,1 -> 15 tiles, 2..8 -> 14 tiles
    const int nbase = chunk * 14 + (chunk < 2 ? chunk : 2);
    const int cnt   = 14 + (chunk < 2 ? 1 : 0);
    const int total = cnt * KT16;

    const uint4* __restrict__ gA = g_hF + (size_t)mtile * 8 * KT16 * 32;
    const int ln16 = tid >> 5;

    float acc[4][4][4];
#pragma unroll
    for (int mi = 0; mi < 4; mi++)
#pragma unroll
        for (int ni = 0; ni < 4; ni++)
#pragma unroll
            for (int q = 0; q < 4; q++) acc[mi][ni][q] = 0.0f;

    // hoisted exact-DC terms (rows fixed for the whole CTA)
    const float inv = 0.0078125f;       // 1/sqrt(N)
    const int rowW = mtile * 128 + wM * 64;
    float dlo[4], dhi[4];
#pragma unroll
    for (int mi = 0; mi < 4; mi++) {
        dlo[mi] = g_dc[rowW + mi * 16 + g]     * inv;
        dhi[mi] = g_dc[rowW + mi * 16 + g + 8] * inv;
    }

    // B stage issue: (nt, kt) cursor
    int nt_i = nbase, kt_i = 0;
    auto issueB = [&](int slot) {
        cp16(&Bs[(slot * 8 + ln16) * 32 + lane],
             g_MF + ((size_t)(nt_i * 8 + ln16) * KT16 + kt_i) * 32 + lane);
        if (++kt_i == KT16) { kt_i = 0; nt_i++; }
    };

    // Prologue: A (whole tile) + stage 0 in group 0; stage 1 in group 1.
#pragma unroll
    for (int i = tid; i < 8 * KT16 * 32; i += 256)
        cp16(&As[i], gA + i);
    issueB(0);
    CP_COMMIT();
    issueB(1);
    CP_COMMIT();

    int slot_w = 2;
    int nt_c = nbase, kt_c = 0;

    for (int s = 0; s < total; s++) {
        if (s + 2 < total) { issueB(slot_w); slot_w = (slot_w + 1) & 3; }
        CP_COMMIT();
        CP_WAIT(2);
        __syncthreads();

        const int slot = s & 3;
        uint4 af[4], bf[2];
#pragma unroll
        for (int mi = 0; mi < 4; mi++)
            af[mi] = As[((wM * 4 + mi) * KT16 + kt_c) * 32 + lane];
#pragma unroll
        for (int p = 0; p < 2; p++)
            bf[p] = Bs[(slot * 8 + wN * 2 + p) * 32 + lane];

#pragma unroll
        for (int mi = 0; mi < 4; mi++) {
            unsigned a[4] = { af[mi].x, af[mi].y, af[mi].z, af[mi].w };
#pragma unroll
            for (int ni = 0; ni < 4; ni++) {
                const uint4& q = bf[ni >> 1];
                unsigned b[2];
                if (ni & 1) { b[0] = q.z; b[1] = q.w; }
                else        { b[0] = q.x; b[1] = q.y; }
                mma_f16(acc[mi][ni], a, b);
            }
        }

        if (++kt_c == KT16) {
            // tile epilogue: add exact DC, store, reset accumulators
            kt_c = 0;
            const int colW = nt_c * 128 + wN * 32;
#pragma unroll
            for (int mi = 0; mi < 4; mi++) {
                int r = rowW + mi * 16 + g;
#pragma unroll
                for (int ni = 0; ni < 4; ni++) {
                    int c = colW + (ni >> 1) * 16 + (ni & 1) * 8 + 2 * t;
                    *(float2*)&out[(size_t)r * NN + c] =
                        make_float2(acc[mi][ni][0] + dlo[mi], acc[mi][ni][1] + dlo[mi]);
                    *(float2*)&out[(size_t)(r + 8) * NN + c] =
                        make_float2(acc[mi][ni][2] + dhi[mi], acc[mi][ni][3] + dhi[mi]);
                    acc[mi][ni][0] = 0.0f; acc[mi][ni][1] = 0.0f;
                    acc[mi][ni][2] = 0.0f; acc[mi][ni][3] = 0.0f;
                }
            }
            nt_c++;
        }
    }
}

// ---------------------------------------------------------------------------
extern "C" void kernel_launch(void* const* d_in, const int* in_sizes, int n_in,
                              void* d_out, int out_size) {
    const float* x      = (const float*)d_in[0];   // [4096, 2048]
    const float* W_proj = (const float*)d_in[1];   // [129, 2048]
    const float* b_proj = (const float*)d_in[2];   // [129]
    const float* Ws     = (const float*)d_in[3];   // [16384, 64]
    float* out = (float*)d_out;                    // [4096, 16384]

    cudaFuncSetAttribute(prep_gemm1_kernel,
                         cudaFuncAttributeMaxDynamicSharedMemorySize, PG1_SMEM);
    cudaFuncSetAttribute(gemm2_persist_kernel,
                         cudaFuncAttributeMaxDynamicSharedMemorySize, G2_SMEM);

    // zero the gemm1 accumulator + m-tile counters (memset nodes)
    void* p = nullptr;
    cudaGetSymbolAddress(&p, g_hacc);
    cudaMemsetAsync(p, 0, sizeof(float) * KPAD * BS_);
    cudaGetSymbolAddress(&p, g_cnt);
    cudaMemsetAsync(p, 0, sizeof(int) * 32);

    // gemm1 (+fused finalize) and basis prep in one launch
    prep_gemm1_kernel<<<G1_BLOCKS + BASIS_BLOCKS, 256, PG1_SMEM>>>(x, W_proj, Ws, b_proj);

    // persistent gemm2: one wave, A resident per CTA
    dim3 g2(9, 32);
    gemm2_persist_kernel<<<g2, 256, G2_SMEM>>>(out);
}

// round 17
// speedup vs baseline: 1.1256x; 1.1256x over previous
#include <cuda_runtime.h>
#include <cuda_fp16.h>
#include <math.h>

// Problem constants
#define BS_      4096
#define IN_DIM_  2048
#define NN       16384
#define TOTAL_D_ 129      // 1 (dc) + 64 (pairs) + 64 (slack)
#define KPAD     136      // gemm1 accumulator row count
#define KT8      8        // gemm2 k-chunks of 16 (128 cols = j=1..128, no pad)

// Scratch (static device globals -- no dynamic allocation allowed)
__device__ float g_hacc[KPAD * BS_];           // [j][b] fp32 gemm1 accumulator
__device__ float g_dc[BS_];                    // exact fp32 h[:,0]
__device__ int   g_cnt[32];                    // per-m-tile split-K counters
// fp16 fragment-shuffled operands for mma.m16n8k16 over c = j-1 in [0,128):
//  g_hF[m16][kt][lane] = {a0,a1,a2,a3} packed half2   (A = h[b][c+1])
//  g_MF[n16][kt][lane] = {b0lo,b1lo,b0hi,b1hi}        (B = M[n][c+1])
__device__ uint4 g_hF[(BS_ / 16) * KT8 * 32];  // 1.0 MB
__device__ uint4 g_MF[(NN  / 16) * KT8 * 32];  // 4.2 MB

__device__ __forceinline__ void mma_f16(float* c, const unsigned* a, const unsigned* b) {
    asm volatile(
        "mma.sync.aligned.m16n8k16.row.col.f32.f16.f16.f32 "
        "{%0,%1,%2,%3}, {%4,%5,%6,%7}, {%8,%9}, {%0,%1,%2,%3};\n"
        : "+f"(c[0]), "+f"(c[1]), "+f"(c[2]), "+f"(c[3])
        : "r"(a[0]), "r"(a[1]), "r"(a[2]), "r"(a[3]), "r"(b[0]), "r"(b[1]));
}

__device__ __forceinline__ void cp16(void* smem, const void* gptr) {
    unsigned s = (unsigned)__cvta_generic_to_shared(smem);
    asm volatile("cp.async.cg.shared.global [%0], [%1], 16;" :: "r"(s), "l"(gptr));
}
#define CP_COMMIT() asm volatile("cp.async.commit_group;")
#define CP_WAIT(n)  asm volatile("cp.async.wait_group %0;" :: "n"(n))

__device__ __forceinline__ unsigned packh2(float lo, float hi) {
    __half2 p = __floats2half2_rn(lo, hi);
    return *(unsigned*)&p;
}

// ---------------------------------------------------------------------------
// Fused kernel 1: blocks [0, 512)   -> gemm1 (cp.async pipelined, fp16 MMA)
//                                      + last-block-per-m-tile fused finalize
//                 blocks [512, 640) -> basis fragments (rotation recurrence)
// g_hacc and g_cnt are zeroed beforehand by cudaMemsetAsync nodes.
// ---------------------------------------------------------------------------
#define G1_BLOCKS    512                       // 32 m-tiles x 16 k-segs
#define BASIS_BLOCKS (NN / 128)                // 128 (128 n-rows per block)
#define ROWW         68                        // basis staging stride (words)

#define RS       20                            // gemm1 tile row stride (words)
#define A_WORDS  (128 * RS)
#define B_WORDS  (144 * RS)
#define STG_W    (A_WORDS + B_WORDS)
#define G1ST     4
#define PG1_SMEM (G1ST * STG_W * 4)            // 87040 bytes

__global__ __launch_bounds__(256, 2)
void prep_gemm1_kernel(const float* __restrict__ x, const float* __restrict__ W,
                       const float* __restrict__ Ws, const float* __restrict__ bp) {
    extern __shared__ __align__(16) float smf[];
    const int tid = threadIdx.x;

    if (blockIdx.x >= G1_BLOCKS) {
        // ---- basis rows (c = j-1 in [0,128)) via rotation recurrence ----
        const int blk = blockIdx.x - G1_BLOCKS;
        unsigned* SW = (unsigned*)smf;                 // 32-bit word view
        const int nl = tid >> 1, half = tid & 1;
        const int n  = blk * 128 + nl;
        unsigned* roww = SW + nl * ROWW;               // 64 data words per row

        const float s2i = 1.41421356237309515f * 0.0078125f;  // sqrt2/128
        const float w0  = 6.28318530717958647692f / (float)NN;

        const int k0 = half ? 17 : 1;
        int m0 = (k0 * n) & (NN - 1); if (m0 >= NN / 2) m0 -= NN;
        int m1 = n;                   if (m1 >= NN / 2) m1 -= NN;
        float c, s, c1, s1;
        sincosf((float)m0 * w0, &s,  &c);    // precise seeds: drift < fp16 ulp
        sincosf((float)m1 * w0, &s1, &c1);
#pragma unroll
        for (int i = 0; i < 16; i++) {
            int k = k0 + i;
            roww[k - 1] = packh2(s2i * c, s2i * s);    // cols 2k-2, 2k-1
            float cn = fmaf(c, c1, -s * s1);
            float sn = fmaf(s, c1,  c * s1);
            c = cn; s = sn;
        }
        // slack cols c = 64..127 (words 32..63)
        const float4* wsrow = (const float4*)(Ws + (size_t)n * 64 + half * 32);
#pragma unroll
        for (int q = 0; q < 8; q++) {
            float4 v = wsrow[q];
            int wslot = 32 + half * 16 + 2 * q;
            roww[wslot]     = packh2(v.x, v.y);
            roww[wslot + 1] = packh2(v.z, v.w);
        }
        __syncthreads();

        // re-emit in mma B-fragment layout
        const int warp = tid >> 5, lane = tid & 31;
        const int g = lane >> 2, t = lane & 3;
        const int rlo = (warp * 16 + g) * ROWW;
        const int rhi = rlo + 8 * ROWW;
        const int n16 = blk * 8 + warp;
#pragma unroll
        for (int kt = 0; kt < KT8; kt++) {
            int o = kt * 8 + t;
            g_MF[((size_t)n16 * KT8 + kt) * 32 + lane] =
                make_uint4(SW[rlo + o], SW[rlo + o + 4],
                           SW[rhi + o], SW[rhi + o + 4]);
        }
        return;
    }

    // ---- gemm1: hacc[j][b] += sum_k x[b][k] * W[j][k] (split-K atomics) ----
    const int bid  = blockIdx.x;
    const int mtile   = bid & 31;
    const int rowBase = mtile * 128;
    const int kSeg    = (bid >> 5) * 128;
    const int warp = tid >> 5, lane = tid & 31;
    const int wM = warp & 3, wN = warp >> 2;
    const int m0 = wM * 32, n0 = wN * 72;
    const int g = lane >> 2, t = lane & 3;

#pragma unroll
    for (int st = 0; st < G1ST; st++)
        for (int i = tid; i < 15 * RS; i += 256)
            smf[st * STG_W + A_WORDS + 129 * RS + i] = 0.0f;

    float acc[2][9][4];
#pragma unroll
    for (int mi = 0; mi < 2; mi++)
#pragma unroll
        for (int ni = 0; ni < 9; ni++)
#pragma unroll
            for (int q = 0; q < 4; q++) acc[mi][ni][q] = 0.0f;

    auto load_stage = [&](int st, int chunk) {
        float* Sa = smf + st * STG_W;
        float* Sb = smf + st * STG_W + A_WORDS;
        const int kBase = kSeg + chunk * 16;
#pragma unroll
        for (int i = tid; i < 512; i += 256) {
            int r = i >> 2, q = i & 3;
            cp16(&Sa[r * RS + 4 * q],
                 &x[(size_t)(rowBase + r) * IN_DIM_ + kBase + 4 * q]);
        }
        for (int i = tid; i < 516; i += 256) {
            int j = i >> 2, q = i & 3;
            cp16(&Sb[j * RS + 4 * q],
                 &W[(size_t)j * IN_DIM_ + kBase + 4 * q]);
        }
    };

#pragma unroll
    for (int s = 0; s < 2; s++) { load_stage(s, s); CP_COMMIT(); }

    for (int kc = 0; kc < 8; kc++) {
        if (kc + 2 < 8) load_stage((kc + 2) % G1ST, kc + 2);
        CP_COMMIT();
        CP_WAIT(2);
        __syncthreads();

        const float* Sa = smf + (kc % G1ST) * STG_W;
        const float* Sb = smf + (kc % G1ST) * STG_W + A_WORDS;

        unsigned a[2][4], b[9][2];
#pragma unroll
        for (int mi = 0; mi < 2; mi++) {
            int r = m0 + mi * 16 + g;
            float2 v0 = *(const float2*)&Sa[(r)     * RS + 2 * t];
            float2 v1 = *(const float2*)&Sa[(r + 8) * RS + 2 * t];
            float2 v2 = *(const float2*)&Sa[(r)     * RS + 2 * t + 8];
            float2 v3 = *(const float2*)&Sa[(r + 8) * RS + 2 * t + 8];
            a[mi][0] = packh2(v0.x, v0.y);
            a[mi][1] = packh2(v1.x, v1.y);
            a[mi][2] = packh2(v2.x, v2.y);
            a[mi][3] = packh2(v3.x, v3.y);
        }
#pragma unroll
        for (int ni = 0; ni < 9; ni++) {
            int c = n0 + ni * 8 + g;
            float2 v0 = *(const float2*)&Sb[c * RS + 2 * t];
            float2 v1 = *(const float2*)&Sb[c * RS + 2 * t + 8];
            b[ni][0] = packh2(v0.x, v0.y);
            b[ni][1] = packh2(v1.x, v1.y);
        }
#pragma unroll
        for (int mi = 0; mi < 2; mi++)
#pragma unroll
            for (int ni = 0; ni < 9; ni++)
                mma_f16(acc[mi][ni], a[mi], b[ni]);
    }

#pragma unroll
    for (int mi = 0; mi < 2; mi++) {
        int r = rowBase + m0 + mi * 16 + g;
#pragma unroll
        for (int ni = 0; ni < 9; ni++) {
            int col = n0 + ni * 8 + 2 * t;
            if (col < KPAD) {
                atomicAdd(&g_hacc[(size_t)col * BS_ + r],           acc[mi][ni][0]);
                atomicAdd(&g_hacc[(size_t)(col + 1) * BS_ + r],     acc[mi][ni][1]);
                atomicAdd(&g_hacc[(size_t)col * BS_ + r + 8],       acc[mi][ni][2]);
                atomicAdd(&g_hacc[(size_t)(col + 1) * BS_ + r + 8], acc[mi][ni][3]);
            }
        }
    }

    // ---- fused finalize: last split-K block of this m-tile emits g_hF ----
    __threadfence();
    __shared__ int s_win;
    if (tid == 0) s_win = (atomicAdd(&g_cnt[mtile], 1) == 15);
    __syncthreads();
    if (!s_win) return;
    __threadfence();

    if (tid < 128)                                        // exact fp32 DC
        g_dc[rowBase + tid] = g_hacc[rowBase + tid] + __ldg(&bp[0]);

    const int m16 = mtile * 8 + warp;    // warp -> m16 within this tile
#pragma unroll
    for (int kt = 0; kt < KT8; kt++) {
        int j0 = 16 * kt + 2 * t + 1;    // j = c + 1
        unsigned r[4];
#pragma unroll
        for (int ksel = 0; ksel < 2; ksel++) {
            int ja = j0 + ksel * 8, jb = ja + 1;
#pragma unroll
            for (int rsel = 0; rsel < 2; rsel++) {
                int b = m16 * 16 + rsel * 8 + g;
                float va = g_hacc[(size_t)ja * BS_ + b] + __ldg(&bp[ja]);
                float vb = g_hacc[(size_t)jb * BS_ + b] + __ldg(&bp[jb]);
                r[ksel * 2 + rsel] = packh2(va, vb);
            }
        }
        g_hF[((size_t)m16 * KT8 + kt) * 32 + lane] = make_uint4(r[0], r[1], r[2], r[3]);
    }
}

// ---------------------------------------------------------------------------
// GEMM2 (fp16 MMA): out[b][n] = sum_c h[b][c+1] * M[n][c+1] + dc[b]/128
// Block tile 128(m) x 128(n); 256 threads, 8 warps 2(m) x 4(n); warp 64x32.
// A resident (32KB) + B 4-stage ring (16KB) = 48KB -> 2 blocks/SM.
// cp.async issued 2 stages ahead -> ONE __syncthreads per k-iteration; 8 iters.
// ---------------------------------------------------------------------------
#define ST 4
#define G2_SMEM ((8 * KT8 * 32 + ST * 8 * 32) * 16)    // 49152 bytes
__global__ __launch_bounds__(256, 2)
void gemm2_frag_kernel(float* __restrict__ out) {
    extern __shared__ uint4 smem[];
    uint4* As = smem;                  // [m16][kt][lane] = [8][8][32]
    uint4* Bs = smem + 8 * KT8 * 32;   // [st][n16][lane] = [ST][8][32]

    const int ntile = blockIdx.x;      // 0..127
    const int mtile = blockIdx.y;      // 0..31
    const int tid  = threadIdx.x;
    const int warp = tid >> 5, lane = tid & 31;
    const int wM = warp & 1, wN = warp >> 1;     // 2(m) x 4(n)
    const int g = lane >> 2, t = lane & 3;

    const uint4* __restrict__ gA = g_hF + (size_t)mtile * 8 * KT8 * 32;
    const uint4* __restrict__ gB = g_MF + (size_t)ntile * 8 * KT8 * 32;

    const int ln16 = tid >> 5;

    float acc[4][4][4];
#pragma unroll
    for (int mi = 0; mi < 4; mi++)
#pragma unroll
        for (int ni = 0; ni < 4; ni++)
#pragma unroll
            for (int q = 0; q < 4; q++) acc[mi][ni][q] = 0.0f;

    // Prologue: whole-K A tile (group 0), then B stages 0 and 1.
#pragma unroll
    for (int i = tid; i < 8 * KT8 * 32; i += 256)
        cp16(&As[i], gA + i);
    CP_COMMIT();
#pragma unroll
    for (int s = 0; s < 2; s++) {
        cp16(&Bs[(s * 8 + ln16) * 32 + lane],
             gB + ((size_t)ln16 * KT8 + s) * 32 + lane);
        CP_COMMIT();
    }

    for (int kt = 0; kt < KT8; kt++) {
        if (kt + 2 < KT8) {
            int st2 = (kt + 2) % ST;
            cp16(&Bs[(st2 * 8 + ln16) * 32 + lane],
                 gB + ((size_t)ln16 * KT8 + kt + 2) * 32 + lane);
        }
        CP_COMMIT();
        CP_WAIT(2);
        __syncthreads();

        const int st = kt % ST;
        uint4 af[4], bf[2];
#pragma unroll
        for (int mi = 0; mi < 4; mi++)
            af[mi] = As[((wM * 4 + mi) * KT8 + kt) * 32 + lane];
#pragma unroll
        for (int p = 0; p < 2; p++)
            bf[p] = Bs[(st * 8 + wN * 2 + p) * 32 + lane];

#pragma unroll
        for (int mi = 0; mi < 4; mi++) {
            unsigned a[4] = { af[mi].x, af[mi].y, af[mi].z, af[mi].w };
#pragma unroll
            for (int ni = 0; ni < 4; ni++) {
                const uint4& q = bf[ni >> 1];
                unsigned b[2];
                if (ni & 1) { b[0] = q.z; b[1] = q.w; }
                else        { b[0] = q.x; b[1] = q.y; }
                mma_f16(acc[mi][ni], a, b);
            }
        }
    }

    // epilogue: add exact DC term, write float2 pairs
    const float inv = 0.0078125f;       // 1/sqrt(N)
    const int rowW = mtile * 128 + wM * 64;
    const int colW = ntile * 128 + wN * 32;
#pragma unroll
    for (int mi = 0; mi < 4; mi++) {
        int r = rowW + mi * 16 + g;
        float d0 = g_dc[r] * inv;
        float d1 = g_dc[r + 8] * inv;
#pragma unroll
        for (int ni = 0; ni < 4; ni++) {
            int c = colW + (ni >> 1) * 16 + (ni & 1) * 8 + 2 * t;
            *(float2*)&out[(size_t)r * NN + c] =
                make_float2(acc[mi][ni][0] + d0, acc[mi][ni][1] + d0);
            *(float2*)&out[(size_t)(r + 8) * NN + c] =
                make_float2(acc[mi][ni][2] + d1, acc[mi][ni][3] + d1);
        }
    }
}

// ---------------------------------------------------------------------------
extern "C" void kernel_launch(void* const* d_in, const int* in_sizes, int n_in,
                              void* d_out, int out_size) {
    const float* x      = (const float*)d_in[0];   // [4096, 2048]
    const float* W_proj = (const float*)d_in[1];   // [129, 2048]
    const float* b_proj = (const float*)d_in[2];   // [129]
    const float* Ws     = (const float*)d_in[3];   // [16384, 64]
    float* out = (float*)d_out;                    // [4096, 16384]

    cudaFuncSetAttribute(prep_gemm1_kernel,
                         cudaFuncAttributeMaxDynamicSharedMemorySize, PG1_SMEM);
    cudaFuncSetAttribute(gemm2_frag_kernel,
                         cudaFuncAttributeMaxDynamicSharedMemorySize, G2_SMEM);

    // zero the gemm1 accumulator + m-tile counters (memset nodes)
    void* p = nullptr;
    cudaGetSymbolAddress(&p, g_hacc);
    cudaMemsetAsync(p, 0, sizeof(float) * KPAD * BS_);
    cudaGetSymbolAddress(&p, g_cnt);
    cudaMemsetAsync(p, 0, sizeof(int) * 32);

    // gemm1 (+fused finalize) and basis prep in one launch
    prep_gemm1_kernel<<<G1_BLOCKS + BASIS_BLOCKS, 256, PG1_SMEM>>>(x, W_proj, Ws, b_proj);

    dim3 g2(NN / 128, BS_ / 128);                  // (128 n, 32 m)
    gemm2_frag_kernel<<<g2, 256, G2_SMEM>>>(out);
}